// round 17
// baseline (speedup 1.0000x reference)
#include <cuda_runtime.h>
#include <cuda_fp16.h>
#include <math.h>
#include <stdint.h>

#define N_ENT 100000
#define N_REL 500
#define NT    250000
#define NROWS (2*NT)
#define DIM   128
#define DIN3  384
#define BN_EPS 1e-5f
#define SLOPE 0.01f
#define REL_COPIES 32

// ---------------- static device scratch (zero-initialized at module load) ----
__device__ __align__(16) __half g_PEh[(size_t)N_ENT * 256];            // 51.2 MB fp16 [P0 | P1]
__device__ __align__(16) __half g_enth[(size_t)N_ENT * DIM];           // 25.6 MB fp16 entity table
__device__ __align__(16) __half g_Prh[N_REL * DIM];                    // 128 KB fp16
__device__ __align__(16) float g_hs[(size_t)N_ENT * DIM];              // 51.2 MB raw e*c_pre sums
__device__ __align__(16) float g_ebs[N_ENT];
__device__            int   g_cnt_ent[N_ENT];
__device__            int   g_cnt_rel[N_REL];
__device__ __align__(16) float g_rel_sum[(size_t)REL_COPIES * N_REL * DIM]; // 8.2 MB raw
__device__ __align__(16) float g_rel_e[REL_COPIES * N_REL];
__device__ __align__(16) float g_sum_ent[DIM];
__device__ __align__(16) float g_sumsq_ent[DIM];
__device__ __align__(16) float g_sumsq_rel[DIM];
__device__ __align__(16) __half g_Wf[256 * 128];                       // folded W, fp16, [j][k]
__device__ __align__(16) float g_WtR[128 * 128];                       // k-major (rel projection)
__device__ __align__(16) float g_biasp[DIM];
__device__ __align__(16) float g_sum1[DIM];
__device__ __align__(16) float g_sumsq1[DIM];
__device__ __align__(16) float g_s1[DIM];
__device__ __align__(16) float g_b1p[DIM];
__device__ __align__(16) float g_u[DIM];       // s1 * a2w
__device__ float g_dconst;                      // b1p . a2w + a2b

__device__ __forceinline__ void red_add_v4(float* a, float4 v) {
    asm volatile("red.global.add.v4.f32 [%0], {%1,%2,%3,%4};"
                 :: "l"(a), "f"(v.x), "f"(v.y), "f"(v.z), "f"(v.w) : "memory");
}

// bn0 fold math, recomputed inline where needed
__device__ __forceinline__ void bn0_fold(int k, const float* bn0g, const float* bn0b,
                                         float& s, float& moff) {
    float mean, var;
    if (k < 256) {
        mean = g_sum_ent[k & 127] / (float)NROWS;
        var  = g_sumsq_ent[k & 127] / (float)NROWS - mean * mean;
    } else {
        mean = 0.f;
        var  = g_sumsq_rel[k - 256] / (float)NT;   // concat(r,-r): mean 0
    }
    s = bn0g[k] * rsqrtf(var + BN_EPS);
    moff = bn0b[k] - mean * s;
}

// ---------------- mma / cp.async helpers ----------------
__device__ __forceinline__ void ldm4(uint32_t a[4], uint32_t saddr) {
    asm volatile("ldmatrix.sync.aligned.m8n8.x4.shared.b16 {%0,%1,%2,%3}, [%4];"
                 : "=r"(a[0]), "=r"(a[1]), "=r"(a[2]), "=r"(a[3]) : "r"(saddr));
}
__device__ __forceinline__ void mma16816f(float d[4], const uint32_t a[4],
                                          uint32_t b0, uint32_t b1) {
    asm volatile(
        "mma.sync.aligned.m16n8k16.row.col.f32.f16.f16.f32 "
        "{%0,%1,%2,%3},{%4,%5,%6,%7},{%8,%9},{%0,%1,%2,%3};"
        : "+f"(d[0]), "+f"(d[1]), "+f"(d[2]), "+f"(d[3])
        : "r"(a[0]), "r"(a[1]), "r"(a[2]), "r"(a[3]), "r"(b0), "r"(b1));
}
__device__ __forceinline__ void cpa16(uint32_t dst, const void* src) {
    asm volatile("cp.async.ca.shared.global [%0], [%1], 16;" :: "r"(dst), "l"(src));
}
__device__ __forceinline__ void cpa_commit() {
    asm volatile("cp.async.commit_group;" ::: "memory");
}
__device__ __forceinline__ void cpa_wait0() {
    asm volatile("cp.async.wait_group 0;" ::: "memory");
}

// ---------------- K0a: entity table -> fp16 (side stream) ----------------
__global__ void k_ent2h(const float* __restrict__ ent) {
    size_t i = (size_t)blockIdx.x * blockDim.x + threadIdx.x;
    size_t stride = (size_t)gridDim.x * blockDim.x;
    for (size_t x = i; x < (size_t)N_ENT * DIM / 4; x += stride) {
        float4 v = ((const float4*)ent)[x];
        __half2 p0 = __floats2half2_rn(v.x, v.y);
        __half2 p1 = __floats2half2_rn(v.z, v.w);
        uint2 pk; pk.x = *(uint32_t*)&p0; pk.y = *(uint32_t*)&p1;
        ((uint2*)g_enth)[x] = pk;
    }
}

// ---------------- K0b: zero accumulators (side stream) ----------------
__global__ void k_zero_big() {
    size_t i = (size_t)blockIdx.x * blockDim.x + threadIdx.x;
    size_t stride = (size_t)gridDim.x * blockDim.x;
    float4 z4 = make_float4(0.f, 0.f, 0.f, 0.f);
    for (size_t x = i; x < (size_t)N_ENT * DIM / 4; x += stride)
        ((float4*)g_hs)[x] = z4;
    for (size_t x = i; x < (size_t)REL_COPIES * N_REL * DIM / 4; x += stride)
        ((float4*)g_rel_sum)[x] = z4;
    for (size_t x = i; x < N_ENT; x += stride) g_ebs[x] = 0.f;
    for (size_t x = i; x < REL_COPIES * N_REL; x += stride) g_rel_e[x] = 0.f;
}

// ---------------- K1: bincount (counters arrive zeroed: static init / self-clean)
__global__ void k_count(const int* __restrict__ trip) {
    int i = blockIdx.x * blockDim.x + threadIdx.x;
    if (i < NT) {
        atomicAdd(&g_cnt_ent[trip[3 * i + 0]], 1);
        atomicAdd(&g_cnt_ent[trip[3 * i + 1]], 1);
        atomicAdd(&g_cnt_rel[trip[3 * i + 2]], 1);
    }
}

// ---------------- K2: count-weighted bn0 stats ----------------
__global__ void k_stats(const float* __restrict__ ent, const float* __restrict__ relw) {
    int t = threadIdx.x; int k = t & 127; int eh = t >> 7;
    float s = 0.f, q = 0.f;
    for (int e = blockIdx.x * 2 + eh; e < N_ENT; e += gridDim.x * 2) {
        float w = (float)g_cnt_ent[e];
        float x = ent[(size_t)e * DIM + k];
        s += w * x; q += w * x * x;
    }
    float qr = 0.f;
    for (int r = blockIdx.x * 2 + eh; r < N_REL; r += gridDim.x * 2) {
        float w = (float)g_cnt_rel[r];
        float x = relw[r * DIM + k];
        qr += w * x * x;
    }
    __shared__ float ss[256], sq[256], sr[256];
    ss[t] = s; sq[t] = q; sr[t] = qr; __syncthreads();
    if (t < 128) {
        atomicAdd(&g_sum_ent[k],   ss[t] + ss[t + 128]);
        atomicAdd(&g_sumsq_ent[k], sq[t] + sq[t + 128]);
        atomicAdd(&g_sumsq_rel[k], sr[t] + sr[t + 128]);
    }
}

// ---------------- K3: prep = build folded weights (blocks>=128) + bias (blocks<128)
__global__ void __launch_bounds__(DIN3) k_prep2(const float* __restrict__ a_w,
                                                const float* __restrict__ a_b,
                                                const float* __restrict__ bn0g,
                                                const float* __restrict__ bn0b) {
    int b = blockIdx.x;
    int t = threadIdx.x;  // 0..383
    if (b >= 128) {
        int idx = (b - 128) * DIN3 + t;
        int j  = idx / DIN3;
        int kk = idx % DIN3;
        float s, moff;
        bn0_fold(kk, bn0g, bn0b, s, moff);
        float v = a_w[idx] * s;
        if (kk < 256) {
            int wr = (kk < 128) ? j : (128 + j);
            int wk = kk & 127;
            g_Wf[wr * 128 + wk] = __float2half_rn(v);
        } else {
            g_WtR[(kk - 256) * 128 + j] = v;
        }
    } else {
        int j = b;
        float s, moff;
        bn0_fold(t, bn0g, bn0b, s, moff);
        float v = moff * a_w[j * DIN3 + t];
        __shared__ float red[DIN3];
        red[t] = v; __syncthreads();
        if (t < 128) red[t] += red[t + 256];
        __syncthreads();
        if (t < 128) red[t] += red[t + 128];
        __syncthreads();
        if (t < 64) red[t] += red[t + 64];
        __syncthreads();
        if (t < 32) {
            float x = red[t] + red[t + 32];
            #pragma unroll
            for (int o = 16; o; o >>= 1) x += __shfl_xor_sync(0xffffffffu, x, o);
            if (t == 0) g_biasp[j] = a_b[j] + x;
        }
    }
}

// ---------------- K4: PE GEMM, full-j CTA, cp.async double-buffered E --------
#define WPITCH 136   // fp16 per smem row (272 B) -> conflict-free ldmatrix
#define EPITCH 136   // fp16 per entity smem row
#define OPITCH3 260  // floats per out-staging row (256 j + pad)
#define NBLK   ((N_ENT + 63) / 64)

__global__ void __launch_bounds__(256, 2) k_gemm_pe_mma() {
    extern __shared__ char sm[];
    __half* sW  = (__half*)sm;                 // 256*136 (full W)
    __half* sE0 = sW + 256 * WPITCH;           // 64*136 buffer 0
    __half* sE1 = sE0 + 64 * EPITCH;           // 64*136 buffer 1

    int tid = threadIdx.x, lane = tid & 31, w = tid >> 5;  // 8 warps
    int j0 = w * 32;

    for (int idx = tid; idx < 256 * 16; idx += 256) {
        int j = idx >> 4, s = idx & 15;
        ((uint4*)(sW + j * WPITCH))[s] = ((const uint4*)g_Wf)[j * 16 + s];
    }

    uint32_t sw_base = (uint32_t)__cvta_generic_to_shared(sW);
    uint32_t se_base[2];
    se_base[0] = (uint32_t)__cvta_generic_to_shared(sE0);
    se_base[1] = (uint32_t)__cvta_generic_to_shared(sE1);
    const int arow = lane & 15, acol8 = (lane >> 4) << 3;
    const int g = lane >> 2, t = lane & 3;
    const uint32_t bladdr = (uint32_t)((((lane >> 3) & 2) * 4 + (lane & 7)) * (EPITCH * 2)
                                       + ((lane >> 3) & 1) * 16);

    // issue a 64-row fp16 tile copy (1024 x 16B chunks, 4 per thread)
    auto issue_tile = [&](int bi, int buf) {
        int base = bi * 64;
        #pragma unroll
        for (int k = 0; k < 4; k++) {
            int c = tid + k * 256;
            int e = c >> 4, s = c & 15;
            int row = base + e; if (row >= N_ENT) row = N_ENT - 1;
            cpa16(se_base[buf] + (uint32_t)(e * (EPITCH * 2) + s * 16),
                  (const char*)g_enth + (size_t)row * 256 + s * 16);
        }
        cpa_commit();
    };

    int cur = 0;
    int bi = blockIdx.x;
    if (bi < NBLK) issue_tile(bi, 0);
    __syncthreads();   // also covers sW staging

    for (; bi < NBLK; bi += gridDim.x) {
        cpa_wait0();
        __syncthreads();
        int nbi = bi + gridDim.x;
        if (nbi < NBLK) issue_tile(nbi, cur ^ 1);

        uint32_t seb = se_base[cur];
        float acc[2][8][4];
        #pragma unroll
        for (int jt = 0; jt < 2; jt++)
            #pragma unroll
            for (int nt = 0; nt < 8; nt++)
                #pragma unroll
                for (int p = 0; p < 4; p++) acc[jt][nt][p] = 0.f;

        #pragma unroll
        for (int kt = 0; kt < 8; kt++) {
            uint32_t a0[4], a1[4];
            uint32_t kcol = (uint32_t)((kt * 16 + acol8) * 2);
            ldm4(a0, sw_base + (uint32_t)((j0 + arow) * (WPITCH * 2)) + kcol);
            ldm4(a1, sw_base + (uint32_t)((j0 + 16 + arow) * (WPITCH * 2)) + kcol);
            #pragma unroll
            for (int np = 0; np < 4; np++) {
                uint32_t boff2 = (uint32_t)(np * (16 * EPITCH * 2) + kt * 32) + bladdr;
                uint32_t bb[4];
                ldm4(bb, seb + boff2);
                mma16816f(acc[0][2 * np],     a0, bb[0], bb[1]);
                mma16816f(acc[0][2 * np + 1], a0, bb[2], bb[3]);
                mma16816f(acc[1][2 * np],     a1, bb[0], bb[1]);
                mma16816f(acc[1][2 * np + 1], a1, bb[2], bb[3]);
            }
        }

        // epilogue: stage through the CURRENT (dead) buffer while cp.async fills the other
        float* sOut = (float*)(cur ? sE1 : sE0);
        int base = bi * 64;
        #pragma unroll
        for (int h = 0; h < 4; h++) {
            __syncthreads();
            #pragma unroll
            for (int jt = 0; jt < 2; jt++)
                #pragma unroll
                for (int nl = 0; nl < 2; nl++) {
                    int nt = 2 * h + nl;
                    int e = nl * 8 + 2 * t;
                    int j = j0 + jt * 16 + g;
                    sOut[e * OPITCH3 + j]           = acc[jt][nt][0];
                    sOut[(e + 1) * OPITCH3 + j]     = acc[jt][nt][1];
                    sOut[e * OPITCH3 + j + 8]       = acc[jt][nt][2];
                    sOut[(e + 1) * OPITCH3 + j + 8] = acc[jt][nt][3];
                }
            __syncthreads();
            for (int idx = tid; idx < 16 * 32; idx += 256) {
                int e = idx >> 5, s = idx & 31;
                int row = base + h * 16 + e;
                if (row < N_ENT) {
                    const float* src = &sOut[e * OPITCH3 + s * 8];
                    uint4 pk;
                    __half2 p0 = __floats2half2_rn(src[0], src[1]);
                    __half2 p1 = __floats2half2_rn(src[2], src[3]);
                    __half2 p2 = __floats2half2_rn(src[4], src[5]);
                    __half2 p3 = __floats2half2_rn(src[6], src[7]);
                    pk.x = *(uint32_t*)&p0; pk.y = *(uint32_t*)&p1;
                    pk.z = *(uint32_t*)&p2; pk.w = *(uint32_t*)&p3;
                    ((uint4*)&g_PEh[(size_t)row * 256])[s] = pk;
                }
            }
        }
        __syncthreads();
        cur ^= 1;
    }
}

// ---------------- K4b: Pr table (+ self-clean bn0 stat arrays) ----------------
__global__ void k_gemm_pr(const float* __restrict__ relw) {
    __shared__ float srow[128];
    int r = blockIdx.x; int j = threadIdx.x;
    srow[j] = relw[r * DIM + j];
    __syncthreads();
    float acc = 0.f;
    #pragma unroll 4
    for (int k = 0; k < 128; k++) acc += srow[k] * g_WtR[k * 128 + j];
    g_Prh[r * DIM + j] = __float2half_rn(acc);
    if (r == 0) {  // consumers (k_prep2) have completed; reset for next call
        g_sum_ent[j] = 0.f; g_sumsq_ent[j] = 0.f; g_sumsq_rel[j] = 0.f;
    }
}

// ---------------- raw 5-load gather + conversion split (explicit MLP) --------
struct RawRow { uint2 a0, b0, a1, b1, pr; };

__device__ __forceinline__ void gather_raw(int t0, int t1, int t2, int off, RawRow& r) {
    const char* r0 = (const char*)&g_PEh[(size_t)t0 * 256];
    const char* r1 = (const char*)&g_PEh[(size_t)t1 * 256];
    r.a0 = *(const uint2*)(r0 + off);
    r.b0 = *(const uint2*)(r0 + 256 + off);
    r.a1 = *(const uint2*)(r1 + off);
    r.b1 = *(const uint2*)(r1 + 256 + off);
    r.pr = *(const uint2*)((const char*)&g_Prh[t2 * DIM] + off);
}

__device__ __forceinline__ void cpre_from_raw(const RawRow& r, const float4& bias,
                                              float4& cf, float4& cb) {
    float2 a0l = __half22float2(*(__half2*)&r.a0.x);
    float2 a0h = __half22float2(*(__half2*)&r.a0.y);
    float2 b0l = __half22float2(*(__half2*)&r.b0.x);
    float2 b0h = __half22float2(*(__half2*)&r.b0.y);
    float2 a1l = __half22float2(*(__half2*)&r.a1.x);
    float2 a1h = __half22float2(*(__half2*)&r.a1.y);
    float2 b1l = __half22float2(*(__half2*)&r.b1.x);
    float2 b1h = __half22float2(*(__half2*)&r.b1.y);
    float2 prl = __half22float2(*(__half2*)&r.pr.x);
    float2 prh = __half22float2(*(__half2*)&r.pr.y);
    cf.x = a0l.x + b1l.x + prl.x + bias.x;  cb.x = a1l.x + b0l.x - prl.x + bias.x;
    cf.y = a0l.y + b1l.y + prl.y + bias.y;  cb.y = a1l.y + b0l.y - prl.y + bias.y;
    cf.z = a0h.x + b1h.x + prh.x + bias.z;  cb.z = a1h.x + b0h.x - prh.x + bias.z;
    cf.w = a0h.y + b1h.y + prh.y + bias.w;  cb.w = a1h.y + b0h.y - prh.y + bias.w;
}

__device__ __forceinline__ void gather_cpre(int t0, int t1, int t2, int off,
                                            const float4& bias,
                                            float4& cf, float4& cb) {
    RawRow r;
    gather_raw(t0, t1, t2, off, r);
    cpre_from_raw(r, bias, cf, cb);
}

// ---------------- passA: bn1 column stats ----------------
__global__ void k_passA(const int* __restrict__ trip) {
    __shared__ float ssum[128], sssq[128];
    int t = threadIdx.x;
    if (t < 128) { ssum[t] = 0.f; sssq[t] = 0.f; }
    __syncthreads();
    int lane = t & 31, wid = t >> 5;
    int gwarp = blockIdx.x * 8 + wid;
    int nwarps = gridDim.x * 8;
    float4 ls = make_float4(0, 0, 0, 0), lq = make_float4(0, 0, 0, 0);
    const float4 bias = ((const float4*)g_biasp)[lane];
    const int off = lane * 8;

    #pragma unroll 4
    for (int i = gwarp; i < NT; i += nwarps) {
        int t0 = trip[3 * i], t1 = trip[3 * i + 1], t2 = trip[3 * i + 2];
        float4 cf, cb;
        gather_cpre(t0, t1, t2, off, bias, cf, cb);
        ls.x += cf.x + cb.x;  lq.x += cf.x * cf.x + cb.x * cb.x;
        ls.y += cf.y + cb.y;  lq.y += cf.y * cf.y + cb.y * cb.y;
        ls.z += cf.z + cb.z;  lq.z += cf.z * cf.z + cb.z * cb.z;
        ls.w += cf.w + cb.w;  lq.w += cf.w * cf.w + cb.w * cb.w;
    }
    atomicAdd(&ssum[4 * lane + 0], ls.x); atomicAdd(&sssq[4 * lane + 0], lq.x);
    atomicAdd(&ssum[4 * lane + 1], ls.y); atomicAdd(&sssq[4 * lane + 1], lq.y);
    atomicAdd(&ssum[4 * lane + 2], ls.z); atomicAdd(&sssq[4 * lane + 2], lq.z);
    atomicAdd(&ssum[4 * lane + 3], ls.w); atomicAdd(&sssq[4 * lane + 3], lq.w);
    __syncthreads();
    if (t < 128) {
        atomicAdd(&g_sum1[t],   ssum[t]);
        atomicAdd(&g_sumsq1[t], sssq[t]);
    }
}

// ---------------- bn1 finalize (+ self-clean sum1/sumsq1) ----------------
__global__ void k_bn1(const float* __restrict__ bn1g, const float* __restrict__ bn1b,
                      const float* __restrict__ a2w,  const float* __restrict__ a2b) {
    __shared__ float red[128];
    int j = threadIdx.x;
    float mean = g_sum1[j] / (float)NROWS;
    float var  = g_sumsq1[j] / (float)NROWS - mean * mean;
    g_sum1[j] = 0.f; g_sumsq1[j] = 0.f;     // reset for next call
    float s = bn1g[j] * rsqrtf(var + BN_EPS);
    float b = bn1b[j] - mean * s;
    float w = a2w[j];
    g_s1[j]  = s;
    g_b1p[j] = b;
    g_u[j]   = s * w;
    red[j] = b * w;
    __syncthreads();
    for (int o = 64; o; o >>= 1) { if (j < o) red[j] += red[j + o]; __syncthreads(); }
    if (j == 0) g_dconst = red[0] + a2b[0];
}

// ---------------- passB: 2 triplets/warp, explicitly batched gathers ---------
__global__ void k_passB(const int* __restrict__ trip) {
    int lane = threadIdx.x & 31, wid = threadIdx.x >> 5;
    int base = (blockIdx.x * 8 + wid) * 2;
    const float4 bias = ((const float4*)g_biasp)[lane];
    const float4 u = ((const float4*)g_u)[lane];
    const float dc = g_dconst;
    const int off = lane * 8;

    int t0a = trip[3 * base + 0], t1a = trip[3 * base + 1], t2a = trip[3 * base + 2];
    int t0b = trip[3 * base + 3], t1b = trip[3 * base + 4], t2b = trip[3 * base + 5];

    RawRow ra, rb;
    gather_raw(t0a, t1a, t2a, off, ra);
    gather_raw(t0b, t1b, t2b, off, rb);

    float4 cfa, cba;
    cpre_from_raw(ra, bias, cfa, cba);
    float dfa = cfa.x * u.x + cfa.y * u.y + cfa.z * u.z + cfa.w * u.w;
    float dba = cba.x * u.x + cba.y * u.y + cba.z * u.z + cba.w * u.w;
    float4 cfb, cbb;
    cpre_from_raw(rb, bias, cfb, cbb);
    float dfb = cfb.x * u.x + cfb.y * u.y + cfb.z * u.z + cfb.w * u.w;
    float dbb = cbb.x * u.x + cbb.y * u.y + cbb.z * u.z + cbb.w * u.w;

    #pragma unroll
    for (int o = 16; o; o >>= 1) {
        dfa += __shfl_xor_sync(0xffffffffu, dfa, o);
        dba += __shfl_xor_sync(0xffffffffu, dba, o);
        dfb += __shfl_xor_sync(0xffffffffu, dfb, o);
        dbb += __shfl_xor_sync(0xffffffffu, dbb, o);
    }
    dfa += dc; dba += dc; dfb += dc; dbb += dc;
    float lfa = (dfa >= 0.f) ? dfa : SLOPE * dfa;
    float lba = (dba >= 0.f) ? dba : SLOPE * dba;
    float lfb = (dfb >= 0.f) ? dfb : SLOPE * dfb;
    float lbb = (dbb >= 0.f) ? dbb : SLOPE * dbb;
    float efa = __expf(-lfa), eba = __expf(-lba);
    float efb = __expf(-lfb), ebb = __expf(-lbb);

    float4 tfa = make_float4(efa * cfa.x, efa * cfa.y, efa * cfa.z, efa * cfa.w);
    float4 tba = make_float4(eba * cba.x, eba * cba.y, eba * cba.z, eba * cba.w);
    float4 tfb = make_float4(efb * cfb.x, efb * cfb.y, efb * cfb.z, efb * cfb.w);
    float4 tbb = make_float4(ebb * cbb.x, ebb * cbb.y, ebb * cbb.z, ebb * cbb.w);

    int cpa = base & (REL_COPIES - 1);
    int cpb = (base + 1) & (REL_COPIES - 1);
    red_add_v4(&g_hs[(size_t)t0a * DIM + 4 * lane], tfa);
    red_add_v4(&g_hs[(size_t)t1a * DIM + 4 * lane], tba);
    red_add_v4(&g_rel_sum[((size_t)cpa * N_REL + t2a) * DIM + 4 * lane], tfa);
    red_add_v4(&g_hs[(size_t)t0b * DIM + 4 * lane], tfb);
    red_add_v4(&g_hs[(size_t)t1b * DIM + 4 * lane], tbb);
    red_add_v4(&g_rel_sum[((size_t)cpb * N_REL + t2b) * DIM + 4 * lane], tfb);
    if (lane == 0)      atomicAdd(&g_ebs[t0a], efa);
    else if (lane == 1) atomicAdd(&g_ebs[t1a], eba);
    else if (lane == 2) atomicAdd(&g_rel_e[cpa * N_REL + t2a], efa);
    else if (lane == 3) atomicAdd(&g_ebs[t0b], efb);
    else if (lane == 4) atomicAdd(&g_ebs[t1b], ebb);
    else if (lane == 5) atomicAdd(&g_rel_e[cpb * N_REL + t2b], efb);
}

// ---------------- finalize outputs (merged ent+rel, self-clean counters) -----
__global__ void k_out(float* __restrict__ out) {
    int idx = blockIdx.x * blockDim.x + threadIdx.x;
    if (idx < N_ENT * 32) {
        int e = idx >> 5, q = idx & 31;
        int cnt = g_cnt_ent[e];
        float4 res;
        if (cnt == 0) {
            res = make_float4(0.f, 0.f, 0.f, 0.f);
        } else {
            float inv = 1.f / g_ebs[e];
            float4 h = ((const float4*)&g_hs[(size_t)e * DIM])[q];
            float4 s1 = ((const float4*)g_s1)[q];
            float4 b1 = ((const float4*)g_b1p)[q];
            res.x = h.x * inv * s1.x + b1.x;
            res.y = h.y * inv * s1.y + b1.y;
            res.z = h.z * inv * s1.z + b1.z;
            res.w = h.w * inv * s1.w + b1.w;
        }
        ((float4*)out)[idx] = res;
        __syncwarp();
        if (q == 0) g_cnt_ent[e] = 0;   // reset for next call (all lanes read above)
    } else if (idx < N_ENT * 32 + N_REL * 32) {
        int ridx = idx - N_ENT * 32;
        int r = ridx >> 5, q = ridx & 31;
        int cnt = g_cnt_rel[r];
        float4 acc = make_float4(0, 0, 0, 0);
        float esum = 0.f;
        #pragma unroll 4
        for (int cp = 0; cp < REL_COPIES; cp++) {
            float4 v = ((const float4*)&g_rel_sum[((size_t)cp * N_REL + r) * DIM])[q];
            acc.x += v.x; acc.y += v.y; acc.z += v.z; acc.w += v.w;
            esum += g_rel_e[cp * N_REL + r];
        }
        float4 s1 = ((const float4*)g_s1)[q];
        float4 b1 = ((const float4*)g_b1p)[q];
        float inv = 1.f / fmaxf((float)cnt, 1.f);
        acc.x = (acc.x * s1.x + b1.x * esum) * inv;
        acc.y = (acc.y * s1.y + b1.y * esum) * inv;
        acc.z = (acc.z * s1.z + b1.z * esum) * inv;
        acc.w = (acc.w * s1.w + b1.w * esum) * inv;
        ((float4*)(out + (size_t)N_ENT * DIM))[ridx] = acc;
        __syncwarp();
        if (q == 0) g_cnt_rel[r] = 0;   // reset for next call
    }
}

// ---------------- launch (side stream: ent2h + zero_big + gemm_pr) -----------
extern "C" void kernel_launch(void* const* d_in, const int* in_sizes, int n_in,
                              void* d_out, int out_size) {
    const int*   trip = (const int*)d_in[0];
    const float* ent  = (const float*)d_in[1];
    const float* relw = (const float*)d_in[2];
    const float* a_w  = (const float*)d_in[3];
    const float* a_b  = (const float*)d_in[4];
    const float* a2w  = (const float*)d_in[5];
    const float* a2b  = (const float*)d_in[6];
    const float* bn0g = (const float*)d_in[7];
    const float* bn0b = (const float*)d_in[8];
    const float* bn1g = (const float*)d_in[9];
    const float* bn1b = (const float*)d_in[10];
    float* out = (float*)d_out;

    static cudaStream_t s2 = nullptr;
    static cudaEvent_t evFork = nullptr, evEnt = nullptr, evPrep = nullptr, evJoin = nullptr;
    if (!s2) {
        cudaStreamCreateWithFlags(&s2, cudaStreamNonBlocking);
        cudaEventCreateWithFlags(&evFork, cudaEventDisableTiming);
        cudaEventCreateWithFlags(&evEnt,  cudaEventDisableTiming);
        cudaEventCreateWithFlags(&evPrep, cudaEventDisableTiming);
        cudaEventCreateWithFlags(&evJoin, cudaEventDisableTiming);
    }

    const int smem_mma = 256 * WPITCH * 2 + 2 * (64 * EPITCH * 2);  // 104448 B -> 2 CTAs/SM
    cudaFuncSetAttribute(k_gemm_pe_mma, cudaFuncAttributeMaxDynamicSharedMemorySize, smem_mma);

    // fork: fp16 entity table + zeroing on side stream
    cudaEventRecord(evFork, 0);
    cudaStreamWaitEvent(s2, evFork, 0);
    k_ent2h<<<1024, 256, 0, s2>>>(ent);
    cudaEventRecord(evEnt, s2);
    k_zero_big<<<1024, 256, 0, s2>>>();

    // main chain
    k_count<<<(NT + 255) / 256, 256>>>(trip);
    k_stats<<<512, 256>>>(ent, relw);
    k_prep2<<<256, DIN3>>>(a_w, a_b, bn0g, bn0b);
    cudaEventRecord(evPrep, 0);
    cudaStreamWaitEvent(s2, evPrep, 0);
    k_gemm_pr<<<N_REL, 128, 0, s2>>>(relw);
    cudaEventRecord(evJoin, s2);

    cudaStreamWaitEvent(0, evEnt, 0);            // GEMM needs the fp16 entity table
    k_gemm_pe_mma<<<296, 256, smem_mma>>>();
    cudaStreamWaitEvent(0, evJoin, 0);           // join: Prh + zeroed accumulators ready
    k_passA<<<1184, 256>>>(trip);
    k_bn1<<<1, 128>>>(bn1g, bn1b, a2w, a2b);
    k_passB<<<(NT + 15) / 16, 256>>>(trip);
    k_out<<<(N_ENT * 32 + N_REL * 32 + 255) / 256, 256>>>(out);
}